// round 5
// baseline (speedup 1.0000x reference)
#include <cuda_runtime.h>
#include <math.h>

#define NB_   512
#define MS_   8
#define T_    64
#define IN_   360
#define H_    230
#define H2_   460
#define H3_   690
#define OUT_  53
#define ENT_  8
#define B_    4096
#define M_    (B_ * T_)

typedef unsigned long long u64;

__device__ float g_xg[2][M_ * H3_];           // input projection (+b_ih)
__device__ float g_out_buf[M_ * H2_];         // concat(hf,hr), layout [t][b][h]
__device__ float g_h[2][2][B_ * H_];          // ping-pong hidden per dir
__device__ float g_score[M_];                 // word scores [t][b]
__device__ float g_wv[B_ * H2_];              // word vectors
__device__ float g_score2[B_];                // sentence scores

__device__ __forceinline__ u64 pack_dup(float b) {
    u64 r; asm("mov.b64 %0, {%1, %2};" : "=l"(r) : "f"(b), "f"(b)); return r;
}
__device__ __forceinline__ void fma2(u64& acc, u64 a, u64 b) {
    asm("fma.rn.f32x2 %0, %1, %2, %0;" : "+l"(acc) : "l"(a), "l"(b));
}
__device__ __forceinline__ float2 unpk(u64 v) {
    float lo, hi; asm("mov.b64 {%0, %1}, %2;" : "=f"(lo), "=f"(hi) : "l"(v));
    return make_float2(lo, hi);
}
__device__ __forceinline__ float sigm(float x) { return 1.0f / (1.0f + expf(-x)); }

// ---------------- zero: d_out + hidden state --------------------------------
__global__ void zero_kernel(float* out, int n_out) {
    size_t i = (size_t)blockIdx.x * blockDim.x + threadIdx.x;
    if (i < (size_t)n_out) out[i] = 0.0f;
    float* p = &g_h[0][0][0];
    size_t tot = (size_t)2 * 2 * B_ * H_;
    for (size_t j = i; j < tot; j += (size_t)gridDim.x * blockDim.x) p[j] = 0.0f;
}

// ---------------- input projection: xg = x @ W_ih^T + b_ih ------------------
// M=262144, K=360, N=690. Tile 128x64, KT=8, 256 threads.
__global__ __launch_bounds__(256) void input_proj_kernel(
    const float* __restrict__ bag,
    const float* __restrict__ Wf, const float* __restrict__ bf,
    const float* __restrict__ Wr, const float* __restrict__ br)
{
    const int dir = blockIdx.z;
    const float* __restrict__ W    = dir ? Wr : Wf;
    const float* __restrict__ bias = dir ? br : bf;
    float* __restrict__ xg = g_xg[dir];

    const int    n0 = blockIdx.x * 64;
    const size_t m0 = (size_t)blockIdx.y * 128;

    __shared__ float As[8][128];
    __shared__ float Bs[8][64];

    const int tid = threadIdx.x;
    const int tx = tid & 15, ty = tid >> 4;
    const int lrow = tid >> 1, lkk = (tid & 1) * 4;
    const int bn = tid >> 2,  bkk = (tid & 3) * 2;

    u64 acc[4][4];
#pragma unroll
    for (int i = 0; i < 4; i++)
#pragma unroll
        for (int j = 0; j < 4; j++) acc[i][j] = 0ull;

    for (int k0 = 0; k0 < IN_; k0 += 8) {          // 360 % 8 == 0
        const float* ap = bag + ((m0 + lrow) * IN_ + k0 + lkk);
        float2 v0 = *(const float2*)ap;
        float2 v1 = *(const float2*)(ap + 2);
        As[lkk][lrow] = v0.x; As[lkk+1][lrow] = v0.y;
        As[lkk+2][lrow] = v1.x; As[lkk+3][lrow] = v1.y;

        float2 w = make_float2(0.f, 0.f);
        if (n0 + bn < H3_)
            w = *(const float2*)(W + (size_t)(n0 + bn) * IN_ + k0 + bkk);
        Bs[bkk][bn] = w.x; Bs[bkk+1][bn] = w.y;
        __syncthreads();
#pragma unroll
        for (int k = 0; k < 8; k++) {
            u64 a[4];
#pragma unroll
            for (int i = 0; i < 4; i++) a[i] = *(const u64*)&As[k][ty * 8 + i * 2];
#pragma unroll
            for (int j = 0; j < 4; j++) {
                u64 bb = pack_dup(Bs[k][j * 16 + tx]);
#pragma unroll
                for (int i = 0; i < 4; i++) fma2(acc[i][j], a[i], bb);
            }
        }
        __syncthreads();
    }
#pragma unroll
    for (int j = 0; j < 4; j++) {
        int n = n0 + j * 16 + tx;
        if (n >= H3_) continue;
        float bi = bias[n];
#pragma unroll
        for (int i = 0; i < 4; i++) {
            float2 v = unpk(acc[i][j]);
            size_t m = m0 + ty * 8 + i * 2;
            xg[m * H3_ + n]       = v.x + bi;
            xg[(m + 1) * H3_ + n] = v.y + bi;
        }
    }
}

// ---------------- GRU step: hg = h @ W_hh^T, fused gates --------------------
// Per dir: M=4096, K=230. Block = 128 rows x (32 cols x 3 gates).
__global__ __launch_bounds__(256) void gru_step_kernel(int s,
    const float* __restrict__ Whf, const float* __restrict__ bhf,
    const float* __restrict__ Whr, const float* __restrict__ bhr)
{
    const int dir  = blockIdx.z;
    const int tIdx = dir ? (T_ - 1 - s) : s;
    const float* __restrict__ W     = dir ? Whr : Whf;
    const float* __restrict__ bhh   = dir ? bhr : bhf;
    const float* __restrict__ hprev = g_h[dir][s & 1];
    float*       __restrict__ hnext = g_h[dir][(s + 1) & 1];
    const float* __restrict__ xg    = g_xg[dir];

    const int    c0 = blockIdx.x * 32;
    const size_t m0 = (size_t)blockIdx.y * 128;

    __shared__ float As[8][128];
    __shared__ float Bs[8][3][32];

    const int tid = threadIdx.x;
    const int tx = tid & 15, ty = tid >> 4;
    const int lrow = tid >> 1, lkk = (tid & 1) * 4;

    u64 acc[4][6];
#pragma unroll
    for (int i = 0; i < 4; i++)
#pragma unroll
        for (int j = 0; j < 6; j++) acc[i][j] = 0ull;

    for (int k0 = 0; k0 < H_; k0 += 8) {
        const float* ap = hprev + ((m0 + lrow) * H_ + k0 + lkk);
        float2 v0 = (k0 + lkk     < H_) ? *(const float2*)ap       : make_float2(0.f, 0.f);
        float2 v1 = (k0 + lkk + 2 < H_) ? *(const float2*)(ap + 2) : make_float2(0.f, 0.f);
        As[lkk][lrow] = v0.x; As[lkk+1][lrow] = v0.y;
        As[lkk+2][lrow] = v1.x; As[lkk+3][lrow] = v1.y;

        if (tid < 96) {
            int g = tid >> 5, c = tid & 31;
            bool cok = (c0 + c) < H_;
            const float* wp = W + (size_t)(g * H_ + c0 + c) * H_ + k0;
#pragma unroll
            for (int kk = 0; kk < 8; kk += 2) {
                float2 w = (cok && (k0 + kk < H_)) ? *(const float2*)(wp + kk)
                                                   : make_float2(0.f, 0.f);
                Bs[kk][g][c] = w.x; Bs[kk+1][g][c] = w.y;
            }
        }
        __syncthreads();
#pragma unroll
        for (int k = 0; k < 8; k++) {
            u64 a[4];
#pragma unroll
            for (int i = 0; i < 4; i++) a[i] = *(const u64*)&As[k][ty * 8 + i * 2];
#pragma unroll
            for (int g = 0; g < 3; g++) {
                float2 w2 = *(const float2*)&Bs[k][g][tx * 2];
                u64 b0 = pack_dup(w2.x);
                u64 b1 = pack_dup(w2.y);
#pragma unroll
                for (int i = 0; i < 4; i++) fma2(acc[i][g * 2],     a[i], b0);
#pragma unroll
                for (int i = 0; i < 4; i++) fma2(acc[i][g * 2 + 1], a[i], b1);
            }
        }
        __syncthreads();
    }

    const int c = c0 + tx * 2;
    if (c >= H_) return;                           // H_ even: pair never straddles
    const float br0 = bhh[c],          br1 = bhh[c + 1];
    const float bz0 = bhh[H_ + c],     bz1 = bhh[H_ + c + 1];
    const float bn0 = bhh[2 * H_ + c], bn1 = bhh[2 * H_ + c + 1];

#pragma unroll
    for (int i = 0; i < 4; i++) {
        float2 vr0 = unpk(acc[i][0]), vr1 = unpk(acc[i][1]);
        float2 vz0 = unpk(acc[i][2]), vz1 = unpk(acc[i][3]);
        float2 vn0 = unpk(acc[i][4]), vn1 = unpk(acc[i][5]);
#pragma unroll
        for (int half = 0; half < 2; half++) {
            size_t b = m0 + ty * 8 + i * 2 + half;
            float ar0 = half ? vr0.y : vr0.x, ar1 = half ? vr1.y : vr1.x;
            float az0 = half ? vz0.y : vz0.x, az1 = half ? vz1.y : vz1.x;
            float an0 = half ? vn0.y : vn0.x, an1 = half ? vn1.y : vn1.x;

            size_t xbase = (b * T_ + (size_t)tIdx) * H3_;
            float2 axr = *(const float2*)&xg[xbase + c];
            float2 axz = *(const float2*)&xg[xbase + H_ + c];
            float2 axn = *(const float2*)&xg[xbase + 2 * H_ + c];
            float2 hp  = *(const float2*)&hprev[b * H_ + c];

            float r0 = sigm(axr.x + ar0 + br0);
            float r1 = sigm(axr.y + ar1 + br1);
            float z0 = sigm(axz.x + az0 + bz0);
            float z1 = sigm(axz.y + az1 + bz1);
            float nn0 = tanhf(axn.x + r0 * (an0 + bn0));
            float nn1 = tanhf(axn.y + r1 * (an1 + bn1));
            float h0 = (1.f - z0) * nn0 + z0 * hp.x;
            float h1 = (1.f - z1) * nn1 + z1 * hp.y;

            *(float2*)&hnext[b * H_ + c] = make_float2(h0, h1);
            *(float2*)&g_out_buf[((size_t)tIdx * B_ + b) * H2_ + (size_t)dir * H_ + c] =
                make_float2(h0, h1);
        }
    }
}

// ---------------- fused attention score: score[m] = sum_n tanh((A@W)[m,n]+b[n])*p[n]
// which=0: A=g_out_buf (rows=262144) -> g_score ; which=1: A=g_wv (4096) -> g_score2
__global__ __launch_bounds__(256) void attn_score_kernel(int which,
    const float* __restrict__ W, const float* __restrict__ bias,
    const float* __restrict__ proj)
{
    const float* __restrict__ A = which ? g_wv : g_out_buf;
    float* __restrict__ score   = which ? g_score2 : g_score;

    const size_t m0 = (size_t)blockIdx.x * 128;

    __shared__ float As[8][128];
    __shared__ float Bs[8][64];
    __shared__ float red[128][16];

    const int tid = threadIdx.x;
    const int tx = tid & 15, ty = tid >> 4;
    const int lrow = tid >> 1, lkk = (tid & 1) * 4;
    const int bkq = tid >> 5,  bnn = (tid & 31) * 2;

    float sp[8];
#pragma unroll
    for (int i = 0; i < 8; i++) sp[i] = 0.0f;

    for (int n0 = 0; n0 < H2_; n0 += 64) {
        u64 acc[4][4];
#pragma unroll
        for (int i = 0; i < 4; i++)
#pragma unroll
            for (int j = 0; j < 4; j++) acc[i][j] = 0ull;

        for (int k0 = 0; k0 < H2_; k0 += 8) {
            const float* ap = A + ((m0 + lrow) * H2_ + k0 + lkk);
            float2 v0 = (k0 + lkk     < H2_) ? *(const float2*)ap       : make_float2(0.f, 0.f);
            float2 v1 = (k0 + lkk + 2 < H2_) ? *(const float2*)(ap + 2) : make_float2(0.f, 0.f);
            As[lkk][lrow] = v0.x; As[lkk+1][lrow] = v0.y;
            As[lkk+2][lrow] = v1.x; As[lkk+3][lrow] = v1.y;

            float2 w = make_float2(0.f, 0.f);
            if ((k0 + bkq) < H2_ && (n0 + bnn) < H2_)
                w = *(const float2*)(W + (size_t)(k0 + bkq) * H2_ + n0 + bnn);
            Bs[bkq][bnn & 63] = w.x; Bs[bkq][(bnn & 63) + 1] = w.y;
            __syncthreads();
#pragma unroll
            for (int k = 0; k < 8; k++) {
                u64 a[4];
#pragma unroll
                for (int i = 0; i < 4; i++) a[i] = *(const u64*)&As[k][ty * 8 + i * 2];
#pragma unroll
                for (int j = 0; j < 4; j++) {
                    u64 bb = pack_dup(Bs[k][j * 16 + tx]);
#pragma unroll
                    for (int i = 0; i < 4; i++) fma2(acc[i][j], a[i], bb);
                }
            }
            __syncthreads();
        }
#pragma unroll
        for (int j = 0; j < 4; j++) {
            int n = n0 + j * 16 + tx;
            if (n >= H2_) continue;
            float bi = bias[n], pj = proj[n];
#pragma unroll
            for (int i = 0; i < 4; i++) {
                float2 v = unpk(acc[i][j]);
                sp[i * 2]     += tanhf(v.x + bi) * pj;
                sp[i * 2 + 1] += tanhf(v.y + bi) * pj;
            }
        }
    }
#pragma unroll
    for (int i = 0; i < 8; i++) red[ty * 8 + i][tx] = sp[i];
    __syncthreads();
    if (tid < 128) {
        float s = 0.f;
#pragma unroll
        for (int j = 0; j < 16; j++) s += red[tid][j];
        score[m0 + tid] = s;
    }
}

// ---------------- word softmax over t + weighted sum ------------------------
__global__ void word_vec_kernel() {
    int b = blockIdx.x;
    __shared__ float sc[T_], al[T_];
    int tid = threadIdx.x;
    if (tid < T_) sc[tid] = g_score[(size_t)tid * B_ + b];
    __syncthreads();
    float mx = -1e30f;
    for (int t = 0; t < T_; t++) mx = fmaxf(mx, sc[t]);
    float sm = 0.f;
    for (int t = 0; t < T_; t++) sm += expf(sc[t] - mx);
    if (tid < T_) al[tid] = expf(sc[tid] - mx) / sm;
    __syncthreads();
    for (int h = tid; h < H2_; h += blockDim.x) {
        float acc = 0.f;
        for (int t = 0; t < T_; t++)
            acc += al[t] * g_out_buf[((size_t)t * B_ + b) * H2_ + h];
        g_wv[(size_t)b * H2_ + h] = acc;
    }
}

// ---------------- sentence softmax + sent_vec + FC + scatter ----------------
__global__ void sent_fc_scatter_kernel(const int* __restrict__ pairs,
                                       const float* __restrict__ fcW,
                                       const float* __restrict__ fcb,
                                       float* __restrict__ out)
{
    int nb = blockIdx.x;
    int tid = threadIdx.x;
    __shared__ float sv[H2_];

    float sc[MS_], mx = -1e30f;
#pragma unroll
    for (int s = 0; s < MS_; s++) { sc[s] = g_score2[nb * MS_ + s]; mx = fmaxf(mx, sc[s]); }
    float sm = 0.f;
#pragma unroll
    for (int s = 0; s < MS_; s++) sm += expf(sc[s] - mx);
    float be[MS_];
#pragma unroll
    for (int s = 0; s < MS_; s++) be[s] = expf(sc[s] - mx) / sm;

    for (int h = tid; h < H2_; h += blockDim.x) {
        float acc = 0.f;
#pragma unroll
        for (int s = 0; s < MS_; s++)
            acc += be[s] * g_wv[((size_t)(nb * MS_ + s)) * H2_ + h];
        sv[h] = acc;
    }
    __syncthreads();

    int d = pairs[nb * 3], e1 = pairs[nb * 3 + 1], e2 = pairs[nb * 3 + 2];
    size_t base = (((size_t)d * ENT_ + e1) * ENT_ + e2) * OUT_;
    for (int o = tid; o < OUT_; o += blockDim.x) {
        float acc = fcb[o];
        for (int k = 0; k < H2_; k++) acc += sv[k] * fcW[(size_t)o * H2_ + k];
        out[base + o] = acc;
    }
}

// ---------------- launch ----------------------------------------------------
extern "C" void kernel_launch(void* const* d_in, const int* in_sizes, int n_in,
                              void* d_out, int out_size) {
    const float* bag   = (const float*)d_in[0];
    const float* Wihf  = (const float*)d_in[1];
    const float* Whhf  = (const float*)d_in[2];
    const float* bihf  = (const float*)d_in[3];
    const float* bhhf  = (const float*)d_in[4];
    const float* Wihr  = (const float*)d_in[5];
    const float* Whhr  = (const float*)d_in[6];
    const float* bihr  = (const float*)d_in[7];
    const float* bhhr  = (const float*)d_in[8];
    const float* Wword = (const float*)d_in[9];
    const float* bword = (const float*)d_in[10];
    const float* pword = (const float*)d_in[11];
    const float* Wsent = (const float*)d_in[12];
    const float* bsent = (const float*)d_in[13];
    const float* psent = (const float*)d_in[14];
    const float* fcW   = (const float*)d_in[15];
    const float* fcb   = (const float*)d_in[16];
    const int*   pairs = (const int*)d_in[17];
    float* out = (float*)d_out;

    zero_kernel<<<14720, 256>>>(out, out_size);
    input_proj_kernel<<<dim3(11, 2048, 2), 256>>>(bag, Wihf, bihf, Wihr, bihr);
    for (int s = 0; s < T_; s++)
        gru_step_kernel<<<dim3(8, 32, 2), 256>>>(s, Whhf, bhhf, Whhr, bhhr);
    attn_score_kernel<<<M_ / 128, 256>>>(0, Wword, bword, pword);
    word_vec_kernel<<<B_, 128>>>();
    attn_score_kernel<<<B_ / 128, 256>>>(1, Wsent, bsent, psent);
    sent_fc_scatter_kernel<<<NB_, 64>>>(pairs, fcW, fcb, out);
}

// round 6
// speedup vs baseline: 1.4892x; 1.4892x over previous
#include <cuda_runtime.h>
#include <math.h>

#define NB_   512
#define MS_   8
#define T_    64
#define IN_   360
#define H_    230
#define H2_   460
#define H3_   690
#define OUT_  53
#define ENT_  8
#define B_    4096
#define M_    (B_ * T_)

typedef unsigned long long u64;

__device__ float g_xg[2][M_ * H3_];           // input projection (+b_ih)
__device__ float g_out_buf[M_ * H2_];         // concat(hf,hr), layout [t][b][h]
__device__ float g_h[2][2][B_ * H_];          // ping-pong hidden per dir
__device__ float g_score[M_];                 // word scores [t][b]
__device__ float g_wv[B_ * H2_];              // word vectors
__device__ float g_score2[B_];                // sentence scores

__device__ __forceinline__ u64 pack_dup(float b) {
    u64 r; asm("mov.b64 %0, {%1, %2};" : "=l"(r) : "f"(b), "f"(b)); return r;
}
__device__ __forceinline__ void fma2(u64& acc, u64 a, u64 b) {
    asm("fma.rn.f32x2 %0, %1, %2, %0;" : "+l"(acc) : "l"(a), "l"(b));
}
__device__ __forceinline__ float2 unpk(u64 v) {
    float lo, hi; asm("mov.b64 {%0, %1}, %2;" : "=f"(lo), "=f"(hi) : "l"(v));
    return make_float2(lo, hi);
}
__device__ __forceinline__ float sigm(float x) { return 1.0f / (1.0f + __expf(-x)); }

// ---------------- zero: d_out + hidden state --------------------------------
__global__ void zero_kernel(float* out, int n_out) {
    size_t i = (size_t)blockIdx.x * blockDim.x + threadIdx.x;
    if (i < (size_t)n_out) out[i] = 0.0f;
    float* p = &g_h[0][0][0];
    size_t tot = (size_t)2 * 2 * B_ * H_;
    for (size_t j = i; j < tot; j += (size_t)gridDim.x * blockDim.x) p[j] = 0.0f;
}

// ---------------- input projection: xg = x @ W_ih^T + b_ih ------------------
// M=262144, K=360, N=690. Tile 128x64, KT=8, 256 threads, 2-stage pipeline.
__global__ __launch_bounds__(256, 3) void input_proj_kernel(
    const float* __restrict__ bag,
    const float* __restrict__ Wf, const float* __restrict__ bf,
    const float* __restrict__ Wr, const float* __restrict__ br)
{
    const int dir = blockIdx.z;
    const float* __restrict__ W    = dir ? Wr : Wf;
    const float* __restrict__ bias = dir ? br : bf;
    float* __restrict__ xg = g_xg[dir];

    const int    n0 = blockIdx.x * 64;
    const size_t m0 = (size_t)blockIdx.y * 128;

    __shared__ float As[2][8][128];
    __shared__ float Bs[2][8][64];

    const int tid = threadIdx.x;
    const int tx = tid & 15, ty = tid >> 4;
    const int lrow = tid >> 1, lkk = (tid & 1) * 4;
    const int bn = tid >> 2,  bkk = (tid & 3) * 2;
    const bool bok = (n0 + bn) < H3_;

    const float* aptr = bag + ((m0 + lrow) * IN_ + lkk);
    const float* wptr = W + (size_t)(n0 + bn) * IN_ + bkk;

    u64 acc[4][4];
#pragma unroll
    for (int i = 0; i < 4; i++)
#pragma unroll
        for (int j = 0; j < 4; j++) acc[i][j] = 0ull;

    // preload stage 0
    {
        float2 a0 = *(const float2*)aptr;
        float2 a1 = *(const float2*)(aptr + 2);
        float2 w  = bok ? *(const float2*)wptr : make_float2(0.f, 0.f);
        As[0][lkk][lrow] = a0.x; As[0][lkk+1][lrow] = a0.y;
        As[0][lkk+2][lrow] = a1.x; As[0][lkk+3][lrow] = a1.y;
        Bs[0][bkk][bn] = w.x; Bs[0][bkk+1][bn] = w.y;
    }
    __syncthreads();

    const int NIT = IN_ / 8;                       // 45
    for (int it = 0; it < NIT; it++) {
        const int cur = it & 1;
        float2 p0, p1, pw;
        if (it + 1 < NIT) {
            const int k0n = (it + 1) * 8;
            p0 = *(const float2*)(aptr + k0n);
            p1 = *(const float2*)(aptr + k0n + 2);
            pw = bok ? *(const float2*)(wptr + k0n) : make_float2(0.f, 0.f);
        }
#pragma unroll
        for (int k = 0; k < 8; k++) {
            u64 a[4];
#pragma unroll
            for (int i = 0; i < 4; i++) a[i] = *(const u64*)&As[cur][k][ty * 8 + i * 2];
#pragma unroll
            for (int j = 0; j < 4; j++) {
                u64 bb = pack_dup(Bs[cur][k][j * 16 + tx]);
#pragma unroll
                for (int i = 0; i < 4; i++) fma2(acc[i][j], a[i], bb);
            }
        }
        if (it + 1 < NIT) {
            const int nx = cur ^ 1;
            As[nx][lkk][lrow] = p0.x; As[nx][lkk+1][lrow] = p0.y;
            As[nx][lkk+2][lrow] = p1.x; As[nx][lkk+3][lrow] = p1.y;
            Bs[nx][bkk][bn] = pw.x; Bs[nx][bkk+1][bn] = pw.y;
        }
        __syncthreads();
    }
#pragma unroll
    for (int j = 0; j < 4; j++) {
        int n = n0 + j * 16 + tx;
        if (n >= H3_) continue;
        float bi = bias[n];
#pragma unroll
        for (int i = 0; i < 4; i++) {
            float2 v = unpk(acc[i][j]);
            size_t m = m0 + ty * 8 + i * 2;
            xg[m * H3_ + n]       = v.x + bi;
            xg[(m + 1) * H3_ + n] = v.y + bi;
        }
    }
}

// ---------------- GRU step: hg = h @ W_hh^T, fused gates --------------------
// Per dir: M=4096, K=230. Block = 128 rows x (32 cols x 3 gates). 2-stage.
__global__ __launch_bounds__(256, 3) void gru_step_kernel(int s,
    const float* __restrict__ Whf, const float* __restrict__ bhf,
    const float* __restrict__ Whr, const float* __restrict__ bhr)
{
    const int dir  = blockIdx.z;
    const int tIdx = dir ? (T_ - 1 - s) : s;
    const float* __restrict__ W     = dir ? Whr : Whf;
    const float* __restrict__ bhh   = dir ? bhr : bhf;
    const float* __restrict__ hprev = g_h[dir][s & 1];
    float*       __restrict__ hnext = g_h[dir][(s + 1) & 1];
    const float* __restrict__ xg    = g_xg[dir];

    const int    c0 = blockIdx.x * 32;
    const size_t m0 = (size_t)blockIdx.y * 128;

    __shared__ float As[2][8][128];
    __shared__ float Bs[2][8][3][32];

    const int tid = threadIdx.x;
    const int tx = tid & 15, ty = tid >> 4;
    const int lrow = tid >> 1, lkk = (tid & 1) * 4;
    const int bg = tid >> 5, bc = tid & 31;        // for B loads (tid<96)
    const bool cok = (tid < 96) && ((c0 + bc) < H_);
    const float* wp = W + (size_t)(bg * H_ + c0 + bc) * H_;
    const float* ap = hprev + ((m0 + lrow) * H_ + lkk);

    u64 acc[4][6];
#pragma unroll
    for (int i = 0; i < 4; i++)
#pragma unroll
        for (int j = 0; j < 6; j++) acc[i][j] = 0ull;

    const int NIT = (H_ + 7) / 8;                  // 29 (last partial)

    // preload stage 0 (k0=0; no upper-edge risk at k<8)
    {
        float2 a0 = *(const float2*)ap;
        float2 a1 = *(const float2*)(ap + 2);
        As[0][lkk][lrow] = a0.x; As[0][lkk+1][lrow] = a0.y;
        As[0][lkk+2][lrow] = a1.x; As[0][lkk+3][lrow] = a1.y;
        if (tid < 96) {
#pragma unroll
            for (int kk = 0; kk < 8; kk += 2) {
                float2 w = cok ? *(const float2*)(wp + kk) : make_float2(0.f, 0.f);
                Bs[0][kk][bg][bc] = w.x; Bs[0][kk+1][bg][bc] = w.y;
            }
        }
    }
    __syncthreads();

    for (int it = 0; it < NIT; it++) {
        const int cur = it & 1;
        float2 p0 = make_float2(0.f, 0.f), p1 = make_float2(0.f, 0.f);
        float2 pw[4];
        if (it + 1 < NIT) {
            const int k0n = (it + 1) * 8;
            if (k0n + lkk     < H_) p0 = *(const float2*)(ap + k0n);
            if (k0n + lkk + 2 < H_) p1 = *(const float2*)(ap + k0n + 2);
            if (tid < 96) {
#pragma unroll
                for (int kk = 0; kk < 8; kk += 2)
                    pw[kk >> 1] = (cok && (k0n + kk < H_))
                                  ? *(const float2*)(wp + k0n + kk)
                                  : make_float2(0.f, 0.f);
            }
        }
#pragma unroll
        for (int k = 0; k < 8; k++) {
            u64 a[4];
#pragma unroll
            for (int i = 0; i < 4; i++) a[i] = *(const u64*)&As[cur][k][ty * 8 + i * 2];
#pragma unroll
            for (int g = 0; g < 3; g++) {
                float2 w2 = *(const float2*)&Bs[cur][k][g][tx * 2];
                u64 b0 = pack_dup(w2.x);
                u64 b1 = pack_dup(w2.y);
#pragma unroll
                for (int i = 0; i < 4; i++) fma2(acc[i][g * 2],     a[i], b0);
#pragma unroll
                for (int i = 0; i < 4; i++) fma2(acc[i][g * 2 + 1], a[i], b1);
            }
        }
        if (it + 1 < NIT) {
            const int nx = cur ^ 1;
            As[nx][lkk][lrow] = p0.x; As[nx][lkk+1][lrow] = p0.y;
            As[nx][lkk+2][lrow] = p1.x; As[nx][lkk+3][lrow] = p1.y;
            if (tid < 96) {
#pragma unroll
                for (int kk = 0; kk < 8; kk += 2) {
                    Bs[nx][kk][bg][bc] = pw[kk >> 1].x;
                    Bs[nx][kk+1][bg][bc] = pw[kk >> 1].y;
                }
            }
        }
        __syncthreads();
    }

    const int c = c0 + tx * 2;
    if (c >= H_) return;                           // H_ even: pair never straddles
    const float br0 = bhh[c],          br1 = bhh[c + 1];
    const float bz0 = bhh[H_ + c],     bz1 = bhh[H_ + c + 1];
    const float bn0 = bhh[2 * H_ + c], bn1 = bhh[2 * H_ + c + 1];

#pragma unroll
    for (int i = 0; i < 4; i++) {
        float2 vr0 = unpk(acc[i][0]), vr1 = unpk(acc[i][1]);
        float2 vz0 = unpk(acc[i][2]), vz1 = unpk(acc[i][3]);
        float2 vn0 = unpk(acc[i][4]), vn1 = unpk(acc[i][5]);
#pragma unroll
        for (int half = 0; half < 2; half++) {
            size_t b = m0 + ty * 8 + i * 2 + half;
            float ar0 = half ? vr0.y : vr0.x, ar1 = half ? vr1.y : vr1.x;
            float az0 = half ? vz0.y : vz0.x, az1 = half ? vz1.y : vz1.x;
            float an0 = half ? vn0.y : vn0.x, an1 = half ? vn1.y : vn1.x;

            size_t xbase = (b * T_ + (size_t)tIdx) * H3_;
            float2 axr = *(const float2*)&xg[xbase + c];
            float2 axz = *(const float2*)&xg[xbase + H_ + c];
            float2 axn = *(const float2*)&xg[xbase + 2 * H_ + c];
            float2 hp  = *(const float2*)&hprev[b * H_ + c];

            float r0 = sigm(axr.x + ar0 + br0);
            float r1 = sigm(axr.y + ar1 + br1);
            float z0 = sigm(axz.x + az0 + bz0);
            float z1 = sigm(axz.y + az1 + bz1);
            float nn0 = tanhf(axn.x + r0 * (an0 + bn0));
            float nn1 = tanhf(axn.y + r1 * (an1 + bn1));
            float h0 = (1.f - z0) * nn0 + z0 * hp.x;
            float h1 = (1.f - z1) * nn1 + z1 * hp.y;

            *(float2*)&hnext[b * H_ + c] = make_float2(h0, h1);
            *(float2*)&g_out_buf[((size_t)tIdx * B_ + b) * H2_ + (size_t)dir * H_ + c] =
                make_float2(h0, h1);
        }
    }
}

// ---------------- fused attention score: score[m] = sum_n tanh((A@W)[m,n]+b[n])*p[n]
// which=0: A=g_out_buf (rows=262144) -> g_score ; which=1: A=g_wv (4096) -> g_score2
__global__ __launch_bounds__(256, 3) void attn_score_kernel(int which,
    const float* __restrict__ W, const float* __restrict__ bias,
    const float* __restrict__ proj)
{
    const float* __restrict__ A = which ? g_wv : g_out_buf;
    float* __restrict__ score   = which ? g_score2 : g_score;

    const size_t m0 = (size_t)blockIdx.x * 128;

    __shared__ float As[2][8][128];
    __shared__ float Bs[2][8][64];
    __shared__ float red[128][16];

    const int tid = threadIdx.x;
    const int tx = tid & 15, ty = tid >> 4;
    const int lrow = tid >> 1, lkk = (tid & 1) * 4;
    const int bkq = tid >> 5,  bnn = (tid & 31) * 2;

    const float* ap = A + ((m0 + lrow) * H2_ + lkk);

    float sp[8];
#pragma unroll
    for (int i = 0; i < 8; i++) sp[i] = 0.0f;

    const int NIT = (H2_ + 7) / 8;                 // 58 (last partial)

    for (int n0 = 0; n0 < H2_; n0 += 64) {
        u64 acc[4][4];
#pragma unroll
        for (int i = 0; i < 4; i++)
#pragma unroll
            for (int j = 0; j < 4; j++) acc[i][j] = 0ull;

        const bool wok0 = (n0 + bnn) < H2_;
        const float* wpb = W + (size_t)bkq * H2_ + n0 + bnn;

        // preload stage 0 (k0=0 fully valid)
        {
            float2 a0 = *(const float2*)ap;
            float2 a1 = *(const float2*)(ap + 2);
            As[0][lkk][lrow] = a0.x; As[0][lkk+1][lrow] = a0.y;
            As[0][lkk+2][lrow] = a1.x; As[0][lkk+3][lrow] = a1.y;
            float2 w = wok0 ? *(const float2*)wpb : make_float2(0.f, 0.f);
            Bs[0][bkq][bnn] = w.x; Bs[0][bkq][bnn + 1] = w.y;
        }
        __syncthreads();

        for (int it = 0; it < NIT; it++) {
            const int cur = it & 1;
            float2 p0 = make_float2(0.f, 0.f), p1 = make_float2(0.f, 0.f), pw = make_float2(0.f, 0.f);
            if (it + 1 < NIT) {
                const int k0n = (it + 1) * 8;
                if (k0n + lkk     < H2_) p0 = *(const float2*)(ap + k0n);
                if (k0n + lkk + 2 < H2_) p1 = *(const float2*)(ap + k0n + 2);
                if (wok0 && (k0n + bkq) < H2_)
                    pw = *(const float2*)(wpb + (size_t)k0n * H2_);
            }
#pragma unroll
            for (int k = 0; k < 8; k++) {
                u64 a[4];
#pragma unroll
                for (int i = 0; i < 4; i++) a[i] = *(const u64*)&As[cur][k][ty * 8 + i * 2];
#pragma unroll
                for (int j = 0; j < 4; j++) {
                    u64 bb = pack_dup(Bs[cur][k][j * 16 + tx]);
#pragma unroll
                    for (int i = 0; i < 4; i++) fma2(acc[i][j], a[i], bb);
                }
            }
            if (it + 1 < NIT) {
                const int nx = cur ^ 1;
                As[nx][lkk][lrow] = p0.x; As[nx][lkk+1][lrow] = p0.y;
                As[nx][lkk+2][lrow] = p1.x; As[nx][lkk+3][lrow] = p1.y;
                Bs[nx][bkq][bnn] = pw.x; Bs[nx][bkq][bnn + 1] = pw.y;
            }
            __syncthreads();
        }
#pragma unroll
        for (int j = 0; j < 4; j++) {
            int n = n0 + j * 16 + tx;
            if (n >= H2_) continue;
            float bi = bias[n], pj = proj[n];
#pragma unroll
            for (int i = 0; i < 4; i++) {
                float2 v = unpk(acc[i][j]);
                sp[i * 2]     += tanhf(v.x + bi) * pj;
                sp[i * 2 + 1] += tanhf(v.y + bi) * pj;
            }
        }
        __syncthreads();
    }
#pragma unroll
    for (int i = 0; i < 8; i++) red[ty * 8 + i][tx] = sp[i];
    __syncthreads();
    if (tid < 128) {
        float s = 0.f;
#pragma unroll
        for (int j = 0; j < 16; j++) s += red[tid][j];
        score[m0 + tid] = s;
    }
}

// ---------------- word softmax over t + weighted sum ------------------------
__global__ void word_vec_kernel() {
    int b = blockIdx.x;
    __shared__ float sc[T_], al[T_];
    int tid = threadIdx.x;
    if (tid < T_) sc[tid] = g_score[(size_t)tid * B_ + b];
    __syncthreads();
    float mx = -1e30f;
    for (int t = 0; t < T_; t++) mx = fmaxf(mx, sc[t]);
    float sm = 0.f;
    for (int t = 0; t < T_; t++) sm += __expf(sc[t] - mx);
    if (tid < T_) al[tid] = __expf(sc[tid] - mx) / sm;
    __syncthreads();
    for (int h = tid; h < H2_; h += blockDim.x) {
        float acc = 0.f;
        for (int t = 0; t < T_; t++)
            acc += al[t] * g_out_buf[((size_t)t * B_ + b) * H2_ + h];
        g_wv[(size_t)b * H2_ + h] = acc;
    }
}

// ---------------- sentence softmax + sent_vec + FC + scatter ----------------
__global__ void sent_fc_scatter_kernel(const int* __restrict__ pairs,
                                       const float* __restrict__ fcW,
                                       const float* __restrict__ fcb,
                                       float* __restrict__ out)
{
    int nb = blockIdx.x;
    int tid = threadIdx.x;
    __shared__ float sv[H2_];

    float sc[MS_], mx = -1e30f;
#pragma unroll
    for (int s = 0; s < MS_; s++) { sc[s] = g_score2[nb * MS_ + s]; mx = fmaxf(mx, sc[s]); }
    float sm = 0.f;
#pragma unroll
    for (int s = 0; s < MS_; s++) sm += __expf(sc[s] - mx);
    float be[MS_];
#pragma unroll
    for (int s = 0; s < MS_; s++) be[s] = __expf(sc[s] - mx) / sm;

    for (int h = tid; h < H2_; h += blockDim.x) {
        float acc = 0.f;
#pragma unroll
        for (int s = 0; s < MS_; s++)
            acc += be[s] * g_wv[((size_t)(nb * MS_ + s)) * H2_ + h];
        sv[h] = acc;
    }
    __syncthreads();

    int d = pairs[nb * 3], e1 = pairs[nb * 3 + 1], e2 = pairs[nb * 3 + 2];
    size_t base = (((size_t)d * ENT_ + e1) * ENT_ + e2) * OUT_;
    for (int o = tid; o < OUT_; o += blockDim.x) {
        float acc = fcb[o];
        for (int k = 0; k < H2_; k++) acc += sv[k] * fcW[(size_t)o * H2_ + k];
        out[base + o] = acc;
    }
}

// ---------------- launch ----------------------------------------------------
extern "C" void kernel_launch(void* const* d_in, const int* in_sizes, int n_in,
                              void* d_out, int out_size) {
    const float* bag   = (const float*)d_in[0];
    const float* Wihf  = (const float*)d_in[1];
    const float* Whhf  = (const float*)d_in[2];
    const float* bihf  = (const float*)d_in[3];
    const float* bhhf  = (const float*)d_in[4];
    const float* Wihr  = (const float*)d_in[5];
    const float* Whhr  = (const float*)d_in[6];
    const float* bihr  = (const float*)d_in[7];
    const float* bhhr  = (const float*)d_in[8];
    const float* Wword = (const float*)d_in[9];
    const float* bword = (const float*)d_in[10];
    const float* pword = (const float*)d_in[11];
    const float* Wsent = (const float*)d_in[12];
    const float* bsent = (const float*)d_in[13];
    const float* psent = (const float*)d_in[14];
    const float* fcW   = (const float*)d_in[15];
    const float* fcb   = (const float*)d_in[16];
    const int*   pairs = (const int*)d_in[17];
    float* out = (float*)d_out;

    zero_kernel<<<14720, 256>>>(out, out_size);
    input_proj_kernel<<<dim3(11, 2048, 2), 256>>>(bag, Wihf, bihf, Wihr, bihr);
    for (int s = 0; s < T_; s++)
        gru_step_kernel<<<dim3(8, 32, 2), 256>>>(s, Whhf, bhhf, Whhr, bhhr);
    attn_score_kernel<<<M_ / 128, 256>>>(0, Wword, bword, pword);
    word_vec_kernel<<<B_, 128>>>();
    attn_score_kernel<<<B_ / 128, 256>>>(1, Wsent, bsent, psent);
    sent_fc_scatter_kernel<<<NB_, 64>>>(pairs, fcW, fcb, out);
}